// round 1
// baseline (speedup 1.0000x reference)
#include <cuda_runtime.h>
#include <cstdint>

#define B_    2
#define L_    2048
#define D_    1024
#define H_    16
#define HD_   64
#define MTOK  (B_ * L_)      // 4096

// Scratch (device globals: allocation-free per harness rules)
__device__ float g_qkv[(size_t)MTOK * (3 * D_)];   // (B,L,3D)
__device__ float g_attn[(size_t)MTOK * D_];        // (B,L,D)

// ---------------------------------------------------------------------------
// SGEMM + bias: C[M,N] = A[M,K] @ B[K,N] + bias[N]
// 128x128 tile, BK=8, 256 threads, 8x8 per thread in 2x2 quads of 4 (conflict-free)
// Requires M%128==0, N%128==0, K%8==0 (true for all our shapes)
// ---------------------------------------------------------------------------
__global__ __launch_bounds__(256) void sgemm_bias(
    const float* __restrict__ A, const float* __restrict__ Bm,
    const float* __restrict__ bias, float* __restrict__ C,
    int M, int N, int K)
{
    __shared__ float As[8][128];   // transposed A tile: As[k][m]
    __shared__ float Bs[8][128];   // Bs[k][n]

    const int tid  = threadIdx.x;
    const int m0   = blockIdx.y * 128;
    const int n0   = blockIdx.x * 128;
    const int trow = tid >> 4;        // 0..15
    const int tcol = tid & 15;        // 0..15
    const int arow = tid >> 1;        // 0..127
    const int acol = (tid & 1) * 4;   // 0 or 4
    const int brow = tid >> 5;        // 0..7
    const int bcol = (tid & 31) * 4;  // 0..124

    const float* Ap = A  + (size_t)(m0 + arow) * K + acol;
    const float* Bp = Bm + (size_t)brow * N + n0 + bcol;

    float acc[8][8];
#pragma unroll
    for (int i = 0; i < 8; i++)
#pragma unroll
        for (int j = 0; j < 8; j++) acc[i][j] = 0.f;

    for (int k0 = 0; k0 < K; k0 += 8) {
        float4 av = *(const float4*)Ap;
        float4 bv = *(const float4*)Bp;
        As[acol + 0][arow] = av.x;
        As[acol + 1][arow] = av.y;
        As[acol + 2][arow] = av.z;
        As[acol + 3][arow] = av.w;
        *(float4*)&Bs[brow][bcol] = bv;
        __syncthreads();

#pragma unroll
        for (int k = 0; k < 8; k++) {
            float4 a0 = *(const float4*)&As[k][trow * 4];
            float4 a1 = *(const float4*)&As[k][64 + trow * 4];
            float4 b0 = *(const float4*)&Bs[k][tcol * 4];
            float4 b1 = *(const float4*)&Bs[k][64 + tcol * 4];
            float a[8] = {a0.x, a0.y, a0.z, a0.w, a1.x, a1.y, a1.z, a1.w};
            float b[8] = {b0.x, b0.y, b0.z, b0.w, b1.x, b1.y, b1.z, b1.w};
#pragma unroll
            for (int i = 0; i < 8; i++)
#pragma unroll
                for (int j = 0; j < 8; j++)
                    acc[i][j] += a[i] * b[j];
        }
        __syncthreads();

        Ap += 8;
        Bp += (size_t)8 * N;
    }

#pragma unroll
    for (int hi = 0; hi < 2; hi++) {
#pragma unroll
        for (int i = 0; i < 4; i++) {
            const int row = m0 + hi * 64 + trow * 4 + i;
#pragma unroll
            for (int hj = 0; hj < 2; hj++) {
                const int col = n0 + hj * 64 + tcol * 4;
                float4 bb = *(const float4*)&bias[col];
                float4 o;
                o.x = acc[hi * 4 + i][hj * 4 + 0] + bb.x;
                o.y = acc[hi * 4 + i][hj * 4 + 1] + bb.y;
                o.z = acc[hi * 4 + i][hj * 4 + 2] + bb.z;
                o.w = acc[hi * 4 + i][hj * 4 + 3] + bb.w;
                *(float4*)&C[(size_t)row * N + col] = o;
            }
        }
    }
}

// ---------------------------------------------------------------------------
// Flash attention (causal), fp32 online softmax.
// Block = one (b, h, q-tile of 64). 256 threads as 16x16; each thread owns a
// 4x4 subtile of S (rows ty*4.., cols tx*4..) and 4x64/16 = 4x4 of O.
// Row stats reduced via half-warp (width-16) shuffles: lanes with equal ty
// are a contiguous 16-lane segment.
// ---------------------------------------------------------------------------
#define PAD 65
__global__ __launch_bounds__(256) void flash_attn(
    const float* __restrict__ qkv, float* __restrict__ out)
{
    extern __shared__ float sm[];
    float* Qs = sm;                 // [64][PAD], pre-scaled by 1/sqrt(HD)
    float* Ks = sm + 64 * PAD;      // [64][PAD]
    float* Vs = sm + 2 * 64 * PAD;  // [64][PAD]
    float* Ps = sm + 3 * 64 * PAD;  // [64][PAD]

    const int tid = threadIdx.x;
    const int tx  = tid & 15;
    const int ty  = tid >> 4;
    // reverse so the longest blocks (largest qt) launch first
    const int qt  = (int)gridDim.x - 1 - (int)blockIdx.x;
    const int h   = blockIdx.y;
    const int b   = blockIdx.z;
    const int q0  = qt * 64;

    const float* base = qkv + (size_t)b * L_ * (3 * D_) + (size_t)h * HD_;
    // q row m: base + m*3072 ; k: +1024 ; v: +2048

    // Load Q tile (pre-scaled)
#pragma unroll
    for (int rr = 0; rr < 64; rr += 16) {
        const int r = rr + ty;
        float4 v4 = *(const float4*)(base + (size_t)(q0 + r) * (3 * D_) + tx * 4);
        Qs[r * PAD + tx * 4 + 0] = v4.x * 0.125f;
        Qs[r * PAD + tx * 4 + 1] = v4.y * 0.125f;
        Qs[r * PAD + tx * 4 + 2] = v4.z * 0.125f;
        Qs[r * PAD + tx * 4 + 3] = v4.w * 0.125f;
    }

    float m_i[4], l_i[4], acc[4][4];
#pragma unroll
    for (int i = 0; i < 4; i++) {
        m_i[i] = -1e30f;
        l_i[i] = 0.f;
#pragma unroll
        for (int j = 0; j < 4; j++) acc[i][j] = 0.f;
    }

    for (int kt = 0; kt <= qt; kt++) {
        const int k0 = kt * 64;
        __syncthreads();  // previous PV readers done (also covers Q load on iter 0)

        // Load K, V tiles
#pragma unroll
        for (int rr = 0; rr < 64; rr += 16) {
            const int r = rr + ty;
            float4 kv4 = *(const float4*)(base + D_ + (size_t)(k0 + r) * (3 * D_) + tx * 4);
            Ks[r * PAD + tx * 4 + 0] = kv4.x;
            Ks[r * PAD + tx * 4 + 1] = kv4.y;
            Ks[r * PAD + tx * 4 + 2] = kv4.z;
            Ks[r * PAD + tx * 4 + 3] = kv4.w;
            float4 vv4 = *(const float4*)(base + 2 * D_ + (size_t)(k0 + r) * (3 * D_) + tx * 4);
            Vs[r * PAD + tx * 4 + 0] = vv4.x;
            Vs[r * PAD + tx * 4 + 1] = vv4.y;
            Vs[r * PAD + tx * 4 + 2] = vv4.z;
            Vs[r * PAD + tx * 4 + 3] = vv4.w;
        }
        __syncthreads();

        // S = Q @ K^T (Q pre-scaled)
        float s[4][4];
#pragma unroll
        for (int i = 0; i < 4; i++)
#pragma unroll
            for (int j = 0; j < 4; j++) s[i][j] = 0.f;

#pragma unroll 8
        for (int d = 0; d < 64; d++) {
            float qv[4], kv[4];
#pragma unroll
            for (int i = 0; i < 4; i++) qv[i] = Qs[(ty * 4 + i) * PAD + d];
#pragma unroll
            for (int j = 0; j < 4; j++) kv[j] = Ks[(tx * 4 + j) * PAD + d];
#pragma unroll
            for (int i = 0; i < 4; i++)
#pragma unroll
                for (int j = 0; j < 4; j++)
                    s[i][j] += qv[i] * kv[j];
        }

        // Causal mask (only diagonal tile can be partial)
        if (kt == qt) {
#pragma unroll
            for (int i = 0; i < 4; i++)
#pragma unroll
                for (int j = 0; j < 4; j++)
                    if (tx * 4 + j > ty * 4 + i) s[i][j] = -1e30f;
        }

        // Online softmax per row; write P to smem
#pragma unroll
        for (int i = 0; i < 4; i++) {
            float mx = fmaxf(fmaxf(s[i][0], s[i][1]), fmaxf(s[i][2], s[i][3]));
#pragma unroll
            for (int off = 8; off > 0; off >>= 1)
                mx = fmaxf(mx, __shfl_xor_sync(0xffffffffu, mx, off, 16));
            const float mnew = fmaxf(m_i[i], mx);
            const float corr = __expf(m_i[i] - mnew);
            m_i[i] = mnew;

            float rs = 0.f;
#pragma unroll
            for (int j = 0; j < 4; j++) {
                const float p = __expf(s[i][j] - mnew);
                s[i][j] = p;
                rs += p;
            }
#pragma unroll
            for (int off = 8; off > 0; off >>= 1)
                rs += __shfl_xor_sync(0xffffffffu, rs, off, 16);

            l_i[i] = l_i[i] * corr + rs;
#pragma unroll
            for (int j = 0; j < 4; j++) acc[i][j] *= corr;
#pragma unroll
            for (int j = 0; j < 4; j++)
                Ps[(ty * 4 + i) * PAD + tx * 4 + j] = s[i][j];
        }
        __syncthreads();

        // O += P @ V
#pragma unroll 8
        for (int j = 0; j < 64; j++) {
            float pv[4], vv[4];
#pragma unroll
            for (int i = 0; i < 4; i++) pv[i] = Ps[(ty * 4 + i) * PAD + j];
#pragma unroll
            for (int c = 0; c < 4; c++) vv[c] = Vs[j * PAD + tx * 4 + c];
#pragma unroll
            for (int i = 0; i < 4; i++)
#pragma unroll
                for (int c = 0; c < 4; c++)
                    acc[i][c] += pv[i] * vv[c];
        }
    }

    // Normalize and write in (B, L, D) layout (head h occupies cols h*64..)
#pragma unroll
    for (int i = 0; i < 4; i++) {
        const float inv = 1.f / l_i[i];
        float4 o;
        o.x = acc[i][0] * inv;
        o.y = acc[i][1] * inv;
        o.z = acc[i][2] * inv;
        o.w = acc[i][3] * inv;
        *(float4*)(out + (size_t)(b * L_ + q0 + ty * 4 + i) * D_ + h * HD_ + tx * 4) = o;
    }
}

// ---------------------------------------------------------------------------
extern "C" void kernel_launch(void* const* d_in, const int* in_sizes, int n_in,
                              void* d_out, int out_size)
{
    const float* x     = (const float*)d_in[0];
    const float* Wqkv  = (const float*)d_in[1];
    const float* bqkv  = (const float*)d_in[2];
    const float* Wproj = (const float*)d_in[3];
    const float* bproj = (const float*)d_in[4];
    float* out = (float*)d_out;

    float *qkv_p = nullptr, *attn_p = nullptr;
    cudaGetSymbolAddress((void**)&qkv_p, g_qkv);
    cudaGetSymbolAddress((void**)&attn_p, g_attn);

    // 1) QKV projection: (4096 x 1024) @ (1024 x 3072) + bias
    sgemm_bias<<<dim3((3 * D_) / 128, MTOK / 128), 256>>>(
        x, Wqkv, bqkv, qkv_p, MTOK, 3 * D_, D_);

    // 2) Causal flash attention
    const size_t smem = 4 * 64 * PAD * sizeof(float);  // 66,560 B
    cudaFuncSetAttribute(flash_attn, cudaFuncAttributeMaxDynamicSharedMemorySize,
                         (int)smem);
    flash_attn<<<dim3(L_ / 64, H_, B_), 256, smem>>>(qkv_p, attn_p);

    // 3) Output projection: (4096 x 1024) @ (1024 x 1024) + bias
    sgemm_bias<<<dim3(D_ / 128, MTOK / 128), 256>>>(
        attn_p, Wproj, bproj, out, MTOK, D_, D_);
}

// round 3
// speedup vs baseline: 2.4374x; 2.4374x over previous
#include <cuda_runtime.h>
#include <cuda_bf16.h>
#include <cstdint>

#define B_    2
#define L_    2048
#define D_    1024
#define H_    16
#define HD_   64
#define MTOK  (B_ * L_)      // 4096

// ---------------------------------------------------------------------------
// Scratch (device globals)
// ---------------------------------------------------------------------------
__device__ __nv_bfloat16 g_x_hi[(size_t)MTOK * D_];
__device__ __nv_bfloat16 g_x_lo[(size_t)MTOK * D_];
__device__ __nv_bfloat16 g_qkv_hi[(size_t)MTOK * (3 * D_)];
__device__ __nv_bfloat16 g_qkv_lo[(size_t)MTOK * (3 * D_)];
__device__ __nv_bfloat16 g_attn_hi[(size_t)MTOK * D_];
__device__ __nv_bfloat16 g_attn_lo[(size_t)MTOK * D_];
__device__ __nv_bfloat16 g_wqkv_hi[(size_t)(3 * D_) * D_];   // [N,K]
__device__ __nv_bfloat16 g_wqkv_lo[(size_t)(3 * D_) * D_];
__device__ __nv_bfloat16 g_wproj_hi[(size_t)D_ * D_];        // [N,K]
__device__ __nv_bfloat16 g_wproj_lo[(size_t)D_ * D_];

// ---------------------------------------------------------------------------
// Portable ISA helpers (sm_80+; compile for plain sm_103)
// ---------------------------------------------------------------------------
__device__ __forceinline__ uint32_t smem_u32(const void* p) {
    uint32_t a;
    asm("{ .reg .u64 t; cvta.to.shared.u64 t, %1; cvt.u32.u64 %0, t; }" : "=r"(a) : "l"(p));
    return a;
}

#define CPASYNC16(dst, src) \
    asm volatile("cp.async.cg.shared.global [%0], [%1], 16;" :: "r"(dst), "l"(src))
#define CPCOMMIT() asm volatile("cp.async.commit_group;" ::: "memory")
#define CPWAIT(n)  asm volatile("cp.async.wait_group %0;" :: "n"(n) : "memory")

__device__ __forceinline__ void mma_bf16(float* c, const uint32_t* a, const uint32_t* b) {
    asm volatile(
        "mma.sync.aligned.m16n8k16.row.col.f32.bf16.bf16.f32 "
        "{%0,%1,%2,%3},{%4,%5,%6,%7},{%8,%9},{%0,%1,%2,%3};"
        : "+f"(c[0]), "+f"(c[1]), "+f"(c[2]), "+f"(c[3])
        : "r"(a[0]), "r"(a[1]), "r"(a[2]), "r"(a[3]), "r"(b[0]), "r"(b[1]));
}

#define LDMATRIX_X4_TRANS(r0, r1, r2, r3, addr) \
    asm volatile("ldmatrix.sync.aligned.m8n8.x4.trans.shared.b16 {%0,%1,%2,%3}, [%4];" \
        : "=r"(r0), "=r"(r1), "=r"(r2), "=r"(r3) : "r"(addr))

__device__ __forceinline__ float ex2f(float x) {
    float y;
    asm("ex2.approx.f32 %0, %1;" : "=f"(y) : "f"(x));
    return y;
}

__device__ __forceinline__ uint32_t pack_bf16(float lo, float hi) {
    __nv_bfloat162 t = __halves2bfloat162(__float2bfloat16(lo), __float2bfloat16(hi));
    return *(uint32_t*)&t;
}
// split pair (x,y) -> packed hi bf16x2 + packed residual bf16x2
__device__ __forceinline__ void split2(float x, float y, uint32_t& hi, uint32_t& lo) {
    __nv_bfloat16 hx = __float2bfloat16(x), hy = __float2bfloat16(y);
    __nv_bfloat162 th = __halves2bfloat162(hx, hy);
    hi = *(uint32_t*)&th;
    lo = pack_bf16(x - __bfloat162float(hx), y - __bfloat162float(hy));
}

// ---------------------------------------------------------------------------
// fp32 -> bf16 hi/lo split (elementwise)
// ---------------------------------------------------------------------------
__global__ __launch_bounds__(256) void cvt_split(
    const float4* __restrict__ in, __nv_bfloat162* __restrict__ hi,
    __nv_bfloat162* __restrict__ lo, int n4)
{
    int i = blockIdx.x * blockDim.x + threadIdx.x;
    if (i >= n4) return;
    float4 v = in[i];
    uint32_t h0, l0, h1, l1;
    split2(v.x, v.y, h0, l0);
    split2(v.z, v.w, h1, l1);
    ((uint32_t*)hi)[2 * i + 0] = h0;
    ((uint32_t*)hi)[2 * i + 1] = h1;
    ((uint32_t*)lo)[2 * i + 0] = l0;
    ((uint32_t*)lo)[2 * i + 1] = l1;
}

// fp32 [K,N] -> bf16 hi/lo transposed [N,K]
__global__ __launch_bounds__(256) void cvt_split_T(
    const float* __restrict__ W, __nv_bfloat16* __restrict__ hiT,
    __nv_bfloat16* __restrict__ loT, int K, int N)
{
    __shared__ float t[32][33];
    const int n0 = blockIdx.x * 32, k0 = blockIdx.y * 32;
    const int tx = threadIdx.x, ty = threadIdx.y;  // 32 x 8
#pragma unroll
    for (int i = 0; i < 32; i += 8)
        t[ty + i][tx] = W[(size_t)(k0 + ty + i) * N + n0 + tx];
    __syncthreads();
#pragma unroll
    for (int i = 0; i < 32; i += 8) {
        float v = t[tx][ty + i];
        __nv_bfloat16 h = __float2bfloat16(v);
        __nv_bfloat16 l = __float2bfloat16(v - __bfloat162float(h));
        size_t off = (size_t)(n0 + ty + i) * K + k0 + tx;
        hiT[off] = h;
        loT[off] = l;
    }
}

// ---------------------------------------------------------------------------
// bf16x3 GEMM via mma.sync: C[M,N] = (Ahi+Alo)[M,K] @ (Bhi+Blo)[N,K]^T + bias
// 128x128 tile, BK=32, 8 warps (warp tile 32x64), cp.async double buffer.
// Smem row: [hi 64B][lo 64B][pad 16B] = 144B (stride 36 words => conflict-free)
// ---------------------------------------------------------------------------
#define G_STAGE_B   36864                    // (128 A rows + 128 B rows) * 144
#define G_STAGE_W   9216
#define G_BPLANE_W  4608                     // 128*36
#define GEMM_SMEM   (2 * G_STAGE_B)          // 73,728

template<bool SPLIT_OUT>
__global__ __launch_bounds__(256) void gemm_mma(
    const __nv_bfloat16* __restrict__ Ahi, const __nv_bfloat16* __restrict__ Alo,
    const __nv_bfloat16* __restrict__ Bhi, const __nv_bfloat16* __restrict__ Blo,
    const float* __restrict__ bias, float* __restrict__ C,
    __nv_bfloat16* __restrict__ Chi, __nv_bfloat16* __restrict__ Clo,
    int M, int N, int K)
{
    extern __shared__ __align__(16) char smem[];
    uint32_t* sw = (uint32_t*)smem;
    const uint32_t sbase = smem_u32(smem);

    const int tid = threadIdx.x;
    const int wid = tid >> 5, lane = tid & 31;
    const int g = lane >> 2, t4 = lane & 3;
    const int wm = wid & 3, wn = wid >> 2;
    const int m0 = blockIdx.y * 128, n0 = blockIdx.x * 128;

    // per-thread cp.async chunk descriptors (8 chunks/stage)
    const char* srcp[8];
    uint32_t dsto[8];
#pragma unroll
    for (int i = 0; i < 8; i++) {
        const int c = tid + 256 * i;
        const int mat = c >> 10;           // 0=A, 1=B
        const int cc = c & 1023;
        const int row = cc >> 3;
        const int part = (cc >> 2) & 1;    // 0=hi, 1=lo
        const int q = cc & 3;
        dsto[i] = mat * 18432 + row * 144 + part * 64 + q * 16;
        const __nv_bfloat16* bp =
            mat ? (part ? Blo : Bhi) : (part ? Alo : Ahi);
        const int grow = mat ? (n0 + row) : (m0 + row);
        srcp[i] = (const char*)(bp + (size_t)grow * K) + q * 16;
    }

    float acc[2][8][4];
#pragma unroll
    for (int mt = 0; mt < 2; mt++)
#pragma unroll
        for (int nt = 0; nt < 8; nt++)
#pragma unroll
            for (int e = 0; e < 4; e++) acc[mt][nt][e] = 0.f;

    const int nk = K / 32;
    // prologue: stage 0
#pragma unroll
    for (int i = 0; i < 8; i++) CPASYNC16(sbase + dsto[i], srcp[i]);
    CPCOMMIT();

    for (int kc = 0; kc < nk; kc++) {
        __syncthreads();
        if (kc + 1 < nk) {
            const uint32_t sb = sbase + ((kc + 1) & 1) * G_STAGE_B;
#pragma unroll
            for (int i = 0; i < 8; i++)
                CPASYNC16(sb + dsto[i], srcp[i] + (size_t)(kc + 1) * 64);
        }
        CPCOMMIT();
        CPWAIT(1);
        __syncthreads();

        const int wbase = (kc & 1) * G_STAGE_W;
#pragma unroll
        for (int u = 0; u < 2; u++) {
            uint32_t ah[2][4], al[2][4], bh[8][2], bl[8][2];
#pragma unroll
            for (int mt = 0; mt < 2; mt++) {
                const int r0 = wm * 32 + mt * 16 + g;
                const int base = wbase + r0 * 36 + u * 8 + t4;
                ah[mt][0] = sw[base];
                ah[mt][1] = sw[base + 8 * 36];
                ah[mt][2] = sw[base + 4];
                ah[mt][3] = sw[base + 8 * 36 + 4];
                al[mt][0] = sw[base + 16];
                al[mt][1] = sw[base + 8 * 36 + 16];
                al[mt][2] = sw[base + 20];
                al[mt][3] = sw[base + 8 * 36 + 20];
            }
#pragma unroll
            for (int nt = 0; nt < 8; nt++) {
                const int rb = wn * 64 + nt * 8 + g;
                const int base = wbase + G_BPLANE_W + rb * 36 + u * 8 + t4;
                bh[nt][0] = sw[base];
                bh[nt][1] = sw[base + 4];
                bl[nt][0] = sw[base + 16];
                bl[nt][1] = sw[base + 20];
            }
#pragma unroll
            for (int mt = 0; mt < 2; mt++)
#pragma unroll
                for (int nt = 0; nt < 8; nt++) mma_bf16(acc[mt][nt], ah[mt], bh[nt]);
#pragma unroll
            for (int mt = 0; mt < 2; mt++)
#pragma unroll
                for (int nt = 0; nt < 8; nt++) mma_bf16(acc[mt][nt], ah[mt], bl[nt]);
#pragma unroll
            for (int mt = 0; mt < 2; mt++)
#pragma unroll
                for (int nt = 0; nt < 8; nt++) mma_bf16(acc[mt][nt], al[mt], bh[nt]);
        }
    }

    // epilogue
#pragma unroll
    for (int mt = 0; mt < 2; mt++) {
        const int row0 = m0 + wm * 32 + mt * 16 + g;
#pragma unroll
        for (int nt = 0; nt < 8; nt++) {
            const int col = n0 + wn * 64 + nt * 8 + 2 * t4;
            const float b0 = bias[col], b1 = bias[col + 1];
            const float v00 = acc[mt][nt][0] + b0, v01 = acc[mt][nt][1] + b1;
            const float v10 = acc[mt][nt][2] + b0, v11 = acc[mt][nt][3] + b1;
            if (SPLIT_OUT) {
                uint32_t h, l;
                split2(v00, v01, h, l);
                *(uint32_t*)(Chi + (size_t)row0 * N + col) = h;
                *(uint32_t*)(Clo + (size_t)row0 * N + col) = l;
                split2(v10, v11, h, l);
                *(uint32_t*)(Chi + (size_t)(row0 + 8) * N + col) = h;
                *(uint32_t*)(Clo + (size_t)(row0 + 8) * N + col) = l;
            } else {
                *(float2*)(C + (size_t)row0 * N + col) = make_float2(v00, v01);
                *(float2*)(C + (size_t)(row0 + 8) * N + col) = make_float2(v10, v11);
            }
        }
    }
}

// ---------------------------------------------------------------------------
// Flash attention via mma.sync, bf16x2 operands (hi/lo), fp32 softmax.
// CTA: 128 q-rows, 8 warps (16 rows each), k-tiles of 64, cp.async dbl buffer.
// Smem: Qhi/Qlo planes (128 rows x 144B), 2 KV buffers of 4 planes (64 x 144B).
// ---------------------------------------------------------------------------
#define A_QPLANE_B  18432                   // 128*144
#define A_KVPLANE_B 9216                    // 64*144
#define A_KVBUF_B   36864                   // 4 planes
#define A_KVBASE_B  36864                   // after 2 Q planes
#define ATTN_SMEM   (A_KVBASE_B + 2 * A_KVBUF_B)   // 110,592
#define SOFTMAX_CST 0.18033688f             // 0.125 * log2(e)

__global__ __launch_bounds__(256) void attn_mma(
    const __nv_bfloat16* __restrict__ qh_g, const __nv_bfloat16* __restrict__ ql_g,
    __nv_bfloat16* __restrict__ oh_g, __nv_bfloat16* __restrict__ ol_g)
{
    extern __shared__ __align__(16) char smem[];
    uint32_t* sw = (uint32_t*)smem;
    const uint32_t sbase = smem_u32(smem);

    const int tid = threadIdx.x;
    const int wid = tid >> 5, lane = tid & 31;
    const int g = lane >> 2, t4 = lane & 3;
    const int qt = (int)gridDim.x - 1 - (int)blockIdx.x;
    const int h = blockIdx.y, b = blockIdx.z;
    const int q0 = qt * 128;
    const int nkt = q0 / 64 + 2;
    const size_t bL = (size_t)b * L_;

    // --- Q cp.async (8 chunks/thread) ---
#pragma unroll
    for (int i = 0; i < 8; i++) {
        const int c = tid + 256 * i;
        const int row = c >> 4;
        const int part = (c >> 3) & 1;
        const int q = c & 7;
        const uint32_t dst = sbase + part * A_QPLANE_B + row * 144 + q * 16;
        const __nv_bfloat16* sp = part ? ql_g : qh_g;
        CPASYNC16(dst, (const char*)(sp + (bL + q0 + row) * 3072 + h * 64) + q * 16);
    }
    CPCOMMIT();

    // KV chunk descriptors
    uint32_t kv_dsto[8];
    size_t kv_rowoff[8];   // element offset within (b,l) row
    int kv_row[8], kv_part[8];
#pragma unroll
    for (int i = 0; i < 8; i++) {
        const int c = tid + 256 * i;
        const int matv = c >> 10;          // 0=K, 1=V
        const int cc = c & 1023;
        const int row = cc >> 4;
        const int part = (cc >> 3) & 1;
        const int q = cc & 7;
        kv_dsto[i] = matv * 18432 + part * A_KVPLANE_B + row * 144 + q * 16;
        kv_rowoff[i] = (size_t)(1024 + matv * 1024 + h * 64 + q * 8);
        kv_row[i] = row;
        kv_part[i] = part;
    }
    // KV stage 0
#pragma unroll
    for (int i = 0; i < 8; i++) {
        const __nv_bfloat16* sp = kv_part[i] ? ql_g : qh_g;
        CPASYNC16(sbase + A_KVBASE_B + kv_dsto[i],
                  sp + (bL + kv_row[i]) * 3072 + kv_rowoff[i]);
    }
    CPCOMMIT();

    uint32_t qh[4][4], ql[4][4];
    float of[8][4];
    float mr[2] = {-1e30f, -1e30f}, lr[2] = {0.f, 0.f};
#pragma unroll
    for (int nt = 0; nt < 8; nt++)
#pragma unroll
        for (int e = 0; e < 4; e++) of[nt][e] = 0.f;

    for (int kt = 0; kt < nkt; kt++) {
        __syncthreads();
        if (kt + 1 < nkt) {
            const uint32_t sb = sbase + A_KVBASE_B + ((kt + 1) & 1) * A_KVBUF_B;
            const size_t rbase = bL + (size_t)(kt + 1) * 64;
#pragma unroll
            for (int i = 0; i < 8; i++) {
                const __nv_bfloat16* sp = kv_part[i] ? ql_g : qh_g;
                CPASYNC16(sb + kv_dsto[i], sp + (rbase + kv_row[i]) * 3072 + kv_rowoff[i]);
            }
        }
        CPCOMMIT();
        CPWAIT(1);
        __syncthreads();

        if (kt == 0) {
            // load Q fragments (rows wid*16 .. +15)
#pragma unroll
            for (int u = 0; u < 4; u++) {
                const int base = (wid * 16 + g) * 36 + u * 8 + t4;
                qh[u][0] = sw[base];
                qh[u][1] = sw[base + 288];
                qh[u][2] = sw[base + 4];
                qh[u][3] = sw[base + 292];
                ql[u][0] = sw[base + 4608];
                ql[u][1] = sw[base + 4608 + 288];
                ql[u][2] = sw[base + 4608 + 4];
                ql[u][3] = sw[base + 4608 + 292];
            }
        }

        const int k0 = kt * 64;
        const int bufw = (A_KVBASE_B + (kt & 1) * A_KVBUF_B) / 4;

        // S = (Qhi+Qlo)(Khi+Klo)^T  (3 passes)
        float sf[8][4];
#pragma unroll
        for (int nt = 0; nt < 8; nt++)
#pragma unroll
            for (int e = 0; e < 4; e++) sf[nt][e] = 0.f;

#pragma unroll
        for (int u = 0; u < 4; u++) {
#pragma unroll
            for (int nt = 0; nt < 8; nt++) {
                const int base = bufw + (nt * 8 + g) * 36 + u * 8 + t4;
                uint32_t bh[2], bl[2];
                bh[0] = sw[base];
                bh[1] = sw[base + 4];
                bl[0] = sw[base + 2304];
                bl[1] = sw[base + 2308];
                mma_bf16(sf[nt], qh[u], bh);
                mma_bf16(sf[nt], qh[u], bl);
                mma_bf16(sf[nt], ql[u], bh);
            }
        }

        // causal mask (diagonal tiles only)
        const int qr0 = q0 + wid * 16 + g;
        if (k0 + 63 > q0 + wid * 16) {
#pragma unroll
            for (int nt = 0; nt < 8; nt++) {
                const int col = k0 + nt * 8 + 2 * t4;
                if (col > qr0)      sf[nt][0] = -1e30f;
                if (col + 1 > qr0)  sf[nt][1] = -1e30f;
                if (col > qr0 + 8)  sf[nt][2] = -1e30f;
                if (col + 1 > qr0 + 8) sf[nt][3] = -1e30f;
            }
        }

        // online softmax (two row-halves per lane: e 0,1 -> row g; e 2,3 -> row g+8)
#pragma unroll
        for (int hhalf = 0; hhalf < 2; hhalf++) {
            const int e0 = hhalf * 2;
            float mx = -1e30f;
#pragma unroll
            for (int nt = 0; nt < 8; nt++)
                mx = fmaxf(mx, fmaxf(sf[nt][e0], sf[nt][e0 + 1]));
            mx = fmaxf(mx, __shfl_xor_sync(0xffffffffu, mx, 1));
            mx = fmaxf(mx, __shfl_xor_sync(0xffffffffu, mx, 2));
            const float mnew = fmaxf(mr[hhalf], mx);
            const float corr = ex2f((mr[hhalf] - mnew) * SOFTMAX_CST);
            mr[hhalf] = mnew;
            float rs = 0.f;
#pragma unroll
            for (int nt = 0; nt < 8; nt++) {
                const float p0 = ex2f((sf[nt][e0] - mnew) * SOFTMAX_CST);
                const float p1 = ex2f((sf[nt][e0 + 1] - mnew) * SOFTMAX_CST);
                sf[nt][e0] = p0;
                sf[nt][e0 + 1] = p1;
                rs += p0 + p1;
            }
            rs += __shfl_xor_sync(0xffffffffu, rs, 1);
            rs += __shfl_xor_sync(0xffffffffu, rs, 2);
            lr[hhalf] = lr[hhalf] * corr + rs;
#pragma unroll
            for (int nt = 0; nt < 8; nt++) {
                of[nt][e0] *= corr;
                of[nt][e0 + 1] *= corr;
            }
        }

        // O += (Phi+Plo)(Vhi+Vlo)
        const uint32_t vhib = sbase + A_KVBASE_B + (kt & 1) * A_KVBUF_B + 18432;
        const int m4 = lane >> 3;
        const int rowm = (m4 & 1) * 8, colm = (m4 >> 1) * 8;
#pragma unroll
        for (int u = 0; u < 4; u++) {
            uint32_t phi[4], plo[4];
            split2(sf[2 * u][0], sf[2 * u][1], phi[0], plo[0]);
            split2(sf[2 * u][2], sf[2 * u][3], phi[1], plo[1]);
            split2(sf[2 * u + 1][0], sf[2 * u + 1][1], phi[2], plo[2]);
            split2(sf[2 * u + 1][2], sf[2 * u + 1][3], phi[3], plo[3]);
#pragma unroll
            for (int ntp = 0; ntp < 4; ntp++) {
                const uint32_t addr = vhib + (16 * u + rowm + (lane & 7)) * 144
                                    + (ntp * 16 + colm) * 2;
                uint32_t r0, r1, r2, r3, s0, s1, s2, s3;
                LDMATRIX_X4_TRANS(r0, r1, r2, r3, addr);
                LDMATRIX_X4_TRANS(s0, s1, s2, s3, addr + A_KVPLANE_B);
                uint32_t bb[2];
                bb[0] = r0; bb[1] = r1;
                mma_bf16(of[2 * ntp], phi, bb);
                mma_bf16(of[2 * ntp], plo, bb);
                bb[0] = r2; bb[1] = r3;
                mma_bf16(of[2 * ntp + 1], phi, bb);
                mma_bf16(of[2 * ntp + 1], plo, bb);
                bb[0] = s0; bb[1] = s1;
                mma_bf16(of[2 * ntp], phi, bb);
                bb[0] = s2; bb[1] = s3;
                mma_bf16(of[2 * ntp + 1], phi, bb);
            }
        }
    }

    // epilogue: normalize, split hi/lo, store
    const float inv0 = 1.f / lr[0], inv1 = 1.f / lr[1];
    const int qr0 = q0 + wid * 16 + g;
#pragma unroll
    for (int nt = 0; nt < 8; nt++) {
        const int col = h * 64 + nt * 8 + 2 * t4;
        uint32_t hh, ll;
        split2(of[nt][0] * inv0, of[nt][1] * inv0, hh, ll);
        *(uint32_t*)(oh_g + (bL + qr0) * D_ + col) = hh;
        *(uint32_t*)(ol_g + (bL + qr0) * D_ + col) = ll;
        split2(of[nt][2] * inv1, of[nt][3] * inv1, hh, ll);
        *(uint32_t*)(oh_g + (bL + qr0 + 8) * D_ + col) = hh;
        *(uint32_t*)(ol_g + (bL + qr0 + 8) * D_ + col) = ll;
    }
}

// ---------------------------------------------------------------------------
extern "C" void kernel_launch(void* const* d_in, const int* in_sizes, int n_in,
                              void* d_out, int out_size)
{
    const float* x     = (const float*)d_in[0];
    const float* Wqkv  = (const float*)d_in[1];
    const float* bqkv  = (const float*)d_in[2];
    const float* Wproj = (const float*)d_in[3];
    const float* bproj = (const float*)d_in[4];
    float* out = (float*)d_out;

    __nv_bfloat16 *xh, *xl, *qh, *ql, *ah, *al, *wqh, *wql, *wph, *wpl;
    cudaGetSymbolAddress((void**)&xh, g_x_hi);
    cudaGetSymbolAddress((void**)&xl, g_x_lo);
    cudaGetSymbolAddress((void**)&qh, g_qkv_hi);
    cudaGetSymbolAddress((void**)&ql, g_qkv_lo);
    cudaGetSymbolAddress((void**)&ah, g_attn_hi);
    cudaGetSymbolAddress((void**)&al, g_attn_lo);
    cudaGetSymbolAddress((void**)&wqh, g_wqkv_hi);
    cudaGetSymbolAddress((void**)&wql, g_wqkv_lo);
    cudaGetSymbolAddress((void**)&wph, g_wproj_hi);
    cudaGetSymbolAddress((void**)&wpl, g_wproj_lo);

    cudaFuncSetAttribute(gemm_mma<true>,  cudaFuncAttributeMaxDynamicSharedMemorySize, GEMM_SMEM);
    cudaFuncSetAttribute(gemm_mma<false>, cudaFuncAttributeMaxDynamicSharedMemorySize, GEMM_SMEM);
    cudaFuncSetAttribute(attn_mma, cudaFuncAttributeMaxDynamicSharedMemorySize, ATTN_SMEM);

    // 0) precision splits
    const int n4 = MTOK * D_ / 4;
    cvt_split<<<(n4 + 255) / 256, 256>>>((const float4*)x,
                                         (__nv_bfloat162*)xh, (__nv_bfloat162*)xl, n4);
    cvt_split_T<<<dim3((3 * D_) / 32, D_ / 32), dim3(32, 8)>>>(Wqkv, wqh, wql, D_, 3 * D_);
    cvt_split_T<<<dim3(D_ / 32, D_ / 32), dim3(32, 8)>>>(Wproj, wph, wpl, D_, D_);

    // 1) QKV projection -> bf16 hi/lo qkv
    gemm_mma<true><<<dim3((3 * D_) / 128, MTOK / 128), 256, GEMM_SMEM>>>(
        xh, xl, wqh, wql, bqkv, nullptr, qh, ql, MTOK, 3 * D_, D_);

    // 2) causal flash attention -> bf16 hi/lo
    attn_mma<<<dim3(L_ / 128, H_, B_), 256, ATTN_SMEM>>>(qh, ql, ah, al);

    // 3) output projection -> fp32 out
    gemm_mma<false><<<dim3(D_ / 128, MTOK / 128), 256, GEMM_SMEM>>>(
        ah, al, wph, wpl, bproj, out, nullptr, nullptr, MTOK, D_, D_);
}